// round 17
// baseline (speedup 1.0000x reference)
#include <cuda_runtime.h>
#include <cuda_bf16.h>
#include <cstdint>

// Embedding gather: out[b, t, :] = weight[idxes[b, t], :]
// idxes: [8, 2048] int32, weight: [50257, 1024] f32, out: [8,2048,1024] f32
//
// R17: final store-policy cell — __stwt (write-through).
// Ten configurations (LDG/forced-MLP/cp.async/bulk-TMA; tiles 1/2/4/8/16;
// store default/.cs/evict_first/evict_last) all sit at 18.0-18.9us kernel:
// the DRAM write stream is the binder (64MB compulsory writes, ~3.8TB/s
// achieved = write-direction ceiling; 'DRAM 48%' = write-only stream on a
// bidirectional cycle counter). __stwt is the one untested store op: it
// writes through with minimal L2 transit, relieving any LTS write-allocate
// pressure competing with the L2-hot weight reads.
// Shape: R9 optimum — 4 rows/CTA, 4096 CTAs, 256 threads, float4 lanes,
// __ldg reads (weight set L2-resident across graph replays).

#define FEATURES 1024
#define VEC4_PER_ROW (FEATURES / 4)   // 256
#define ROWS_PER_CTA 4

__global__ __launch_bounds__(256) void embedding_gather_stwt_kernel(
    const int* __restrict__ idxes,
    const float4* __restrict__ weight,
    float4* __restrict__ out,
    int n_rows)
{
    const int t = threadIdx.x;                     // 0..255 = column slot
    const int base = blockIdx.x * ROWS_PER_CTA;

    if (base + ROWS_PER_CTA <= n_rows) {
        // One vectorized broadcast index load.
        int4 iv = __ldg((const int4*)(idxes + base));
        int idx[ROWS_PER_CTA] = {iv.x, iv.y, iv.z, iv.w};

        float4 v[ROWS_PER_CTA];
#pragma unroll
        for (int r = 0; r < ROWS_PER_CTA; r++)
            v[r] = __ldg(weight + (size_t)idx[r] * VEC4_PER_ROW + t);

        // Write-through stores: minimal L2 occupancy for the zero-reuse
        // output stream.
#pragma unroll
        for (int r = 0; r < ROWS_PER_CTA; r++)
            __stwt(out + (size_t)(base + r) * VEC4_PER_ROW + t, v[r]);
    } else {
        // Tail (unused at 16384 rows; kept for safety).
        for (int r = 0; r < ROWS_PER_CTA; r++) {
            int row = base + r;
            if (row >= n_rows) break;
            int src = idxes[row];
            __stwt(out + (size_t)row * VEC4_PER_ROW + t,
                   __ldg(weight + (size_t)src * VEC4_PER_ROW + t));
        }
    }
}

extern "C" void kernel_launch(void* const* d_in, const int* in_sizes, int n_in,
                              void* d_out, int out_size)
{
    const int*    idxes  = (const int*)d_in[0];
    const float4* weight = (const float4*)d_in[1];
    float4*       out    = (float4*)d_out;

    int n_rows = in_sizes[0];      // 8 * 2048 = 16384
    int n_ctas = (n_rows + ROWS_PER_CTA - 1) / ROWS_PER_CTA;

    embedding_gather_stwt_kernel<<<n_ctas, 256>>>(idxes, weight, out, n_rows);
}